// round 2
// baseline (speedup 1.0000x reference)
#include <cuda_runtime.h>
#include <cstdint>

#define VOCAB 32000
#define EMB   512
#define HID   1024
#define BATCH 32
#define SEQ   512
#define G4    4096               // 4*HID
#define NTOK  (BATCH*SEQ)        // 16384

// ---------------- scratch (static device allocations only) ----------------
__device__ float g_xproj[(size_t)NTOK * G4];     // 256 MB: [token][gate]
__device__ float g_hbuf[2][BATCH][HID];          // double-buffered h state
__device__ unsigned g_bar_gen;                   // monotonic barrier generation
__device__ unsigned g_bar_cnt;                   // arrival counter (returns to 0)

// =====================================================================
// Kernel 1: x_proj = gather(emb_table, x) @ W_ih^T + (b_ih + b_hh)
// C[16384,4096], K=512. Tiled SGEMM BM=128 BN=64 BK=16, 256 thr, 8x4 microtile.
// =====================================================================
#define BM 128
#define BN 64
#define BK 16

__global__ void __launch_bounds__(256) xproj_kernel(
    const int* __restrict__ x,              // int32 tokens (JAX x64-disabled)
    const float* __restrict__ emb,
    const float* __restrict__ Wih,
    const float* __restrict__ bih,
    const float* __restrict__ bhh)
{
    __shared__ float As[BK][BM];
    __shared__ float Bs[BK][BN];

    const int tid = threadIdx.x;
    const int m0 = blockIdx.y * BM;
    const int n0 = blockIdx.x * BN;

    // A loader: 2 threads per token row, 8 consecutive k each
    const int arow  = tid >> 1;
    const int akoff = (tid & 1) * 8;
    int erow = x[m0 + arow];
    erow = max(0, min(VOCAB - 1, erow));      // crash-proof if dtype theory wrong
    const float* aptr = emb + (size_t)erow * EMB + akoff;

    // B loader: 4 threads per gate row, 4 consecutive k each
    const int brow  = tid >> 2;
    const int bkoff = (tid & 3) * 4;
    const float* bptr = Wih + (size_t)(n0 + brow) * EMB + bkoff;

    const int ty = tid >> 4;        // 0..15 -> 8 rows each
    const int tx = tid & 15;        // 0..15 -> 4 cols each
    const int mt = ty * 8;
    const int nt = tx * 4;

    float acc[8][4];
#pragma unroll
    for (int i = 0; i < 8; i++)
#pragma unroll
        for (int j = 0; j < 4; j++) acc[i][j] = 0.f;

    for (int kt = 0; kt < EMB; kt += BK) {
        float4 a0 = *(const float4*)(aptr + kt);
        float4 a1 = *(const float4*)(aptr + kt + 4);
        float4 bv = *(const float4*)(bptr + kt);
        __syncthreads();
        As[akoff + 0][arow] = a0.x; As[akoff + 1][arow] = a0.y;
        As[akoff + 2][arow] = a0.z; As[akoff + 3][arow] = a0.w;
        As[akoff + 4][arow] = a1.x; As[akoff + 5][arow] = a1.y;
        As[akoff + 6][arow] = a1.z; As[akoff + 7][arow] = a1.w;
        Bs[bkoff + 0][brow] = bv.x; Bs[bkoff + 1][brow] = bv.y;
        Bs[bkoff + 2][brow] = bv.z; Bs[bkoff + 3][brow] = bv.w;
        __syncthreads();
#pragma unroll
        for (int k = 0; k < BK; k++) {
            float af[8], bf[4];
            *(float4*)(af)     = *(const float4*)&As[k][mt];
            *(float4*)(af + 4) = *(const float4*)&As[k][mt + 4];
            *(float4*)(bf)     = *(const float4*)&Bs[k][nt];
#pragma unroll
            for (int i = 0; i < 8; i++)
#pragma unroll
                for (int j = 0; j < 4; j++)
                    acc[i][j] = fmaf(af[i], bf[j], acc[i][j]);
        }
    }

    float bias[4];
#pragma unroll
    for (int j = 0; j < 4; j++) bias[j] = bih[n0 + nt + j] + bhh[n0 + nt + j];
#pragma unroll
    for (int i = 0; i < 8; i++) {
        const size_t row = (size_t)(m0 + mt + i);
        float4 o;
        o.x = acc[i][0] + bias[0];
        o.y = acc[i][1] + bias[1];
        o.z = acc[i][2] + bias[2];
        o.w = acc[i][3] + bias[3];
        *(float4*)&g_xproj[row * G4 + n0 + nt] = o;
    }
}

// =====================================================================
// Kernel 2: persistent LSTM recurrence. 128 blocks (1/SM, all resident),
// block owns 8 j-units; W_hh rows (4 gates x 8 j) cached in smem once.
// Grid barrier per timestep; h double-buffered in global (ldcg/stcg).
// =====================================================================
#define JB   8            // j units per block
#define GROWS 32          // 4*JB weight rows
#define WPAD 1032         // row stride in smem (conflict-free: %32 == 8)
#define KC   256          // K chunk size
#define RT   256          // threads

__device__ __forceinline__ float sigf(float v) {
    return 1.f / (1.f + __expf(-v));
}

__device__ __forceinline__ void grid_barrier(unsigned target) {
    __syncthreads();
    if (threadIdx.x == 0) {
        __threadfence();
        unsigned prev = atomicAdd(&g_bar_cnt, 1u);
        if (prev == gridDim.x - 1) {
            atomicExch(&g_bar_cnt, 0u);
            __threadfence();
            atomicExch(&g_bar_gen, target);
        } else {
            while ((int)(*(volatile unsigned*)&g_bar_gen - target) < 0) { }
        }
        __threadfence();
    }
    __syncthreads();
}

__global__ void __launch_bounds__(RT, 1) lstm_kernel(
    const float* __restrict__ Whh,
    float* __restrict__ out,
    int out_size)
{
    extern __shared__ float sm[];
    float* w_s = sm;                      // [32][WPAD]
    float* hs  = sm + GROWS * WPAD;       // [BATCH][KC]

    const int tid = threadIdx.x;
    const int bid = blockIdx.x;
    const int j0  = bid * JB;

    const unsigned gen0 = *(volatile unsigned*)&g_bar_gen;

    // ---- load this block's W_hh slice into smem (once) ----
    for (int idx = tid; idx < GROWS * (HID / 4); idx += RT) {
        int r   = idx / (HID / 4);
        int k4  = idx % (HID / 4);
        int q   = r >> 3, jl = r & 7;
        float4 v = ((const float4*)Whh)[(size_t)(q * HID + j0 + jl) * (HID / 4) + k4];
        float* dst = w_s + r * WPAD + k4 * 4;
        dst[0] = v.x; dst[1] = v.y; dst[2] = v.z; dst[3] = v.w;
    }

    // thread decomposition: 32 items (jl x batch-group) x 8 K-slices
    const int kslice = tid & 7;
    const int item   = tid >> 3;
    const int jl     = item & 7;
    const int bg     = item >> 3;
    const int b0     = bg * 8;
    const int myb    = b0 + kslice;       // batch this thread owns post-reduce
    const int jg     = j0 + jl;

    const float* wb0 = w_s + (0 * JB + jl) * WPAD;
    const float* wb1 = w_s + (1 * JB + jl) * WPAD;
    const float* wb2 = w_s + (2 * JB + jl) * WPAD;
    const float* wb3 = w_s + (3 * JB + jl) * WPAD;

    float c_reg;

    // ---- t = 0: h_prev = 0 -> gates are just x_proj ----
    {
        const float* xp = g_xproj + (size_t)(myb * SEQ + 0) * G4;
        float gi = xp[0 * HID + jg];
        float gg = xp[2 * HID + jg];
        float go = xp[3 * HID + jg];
        float iv = sigf(gi);
        float gv = tanhf(gg);
        float ov = sigf(go);
        c_reg = iv * gv;                          // f*c0 = 0
        float hv = ov * tanhf(c_reg);
        out[((size_t)myb * SEQ + 0) * HID + jg] = hv;
        __stcg(&g_hbuf[1][myb][jg], hv);
    }
    grid_barrier(gen0 + 1);

    // ---- t = 1 .. 511 ----
    for (int t = 1; t < SEQ; ++t) {
        const float* hsrc = &g_hbuf[t & 1][0][0];

        // prefetch this thread's x_proj values early
        const float* xp = g_xproj + (size_t)(myb * SEQ + t) * G4;
        float xpi = xp[0 * HID + jg];
        float xpf = xp[1 * HID + jg];
        float xpg = xp[2 * HID + jg];
        float xpo = xp[3 * HID + jg];

        float acc[4][8];
#pragma unroll
        for (int q = 0; q < 4; q++)
#pragma unroll
            for (int bb = 0; bb < 8; bb++) acc[q][bb] = 0.f;

        for (int ch = 0; ch < HID / KC; ++ch) {
            __syncthreads();
            // stage h chunk [BATCH][KC] into smem (L2-resident, bypass L1)
            for (int idx = tid; idx < BATCH * KC / 4; idx += RT) {
                int b  = idx >> 6;            // / (KC/4)
                int k4 = idx & 63;
                ((float4*)hs)[idx] =
                    __ldcg(((const float4*)hsrc) + (size_t)b * (HID / 4) + ch * (KC / 4) + k4);
            }
            __syncthreads();

            const float* w0 = wb0 + ch * KC;
            const float* w1 = wb1 + ch * KC;
            const float* w2 = wb2 + ch * KC;
            const float* w3 = wb3 + ch * KC;
#pragma unroll 8
            for (int kk = 0; kk < KC / 8; ++kk) {
                const int kl = kk * 8 + kslice;
                float v0 = w0[kl], v1 = w1[kl], v2 = w2[kl], v3 = w3[kl];
#pragma unroll
                for (int bb = 0; bb < 8; bb++) {
                    float hv = hs[(b0 + bb) * KC + kl];
                    acc[0][bb] = fmaf(v0, hv, acc[0][bb]);
                    acc[1][bb] = fmaf(v1, hv, acc[1][bb]);
                    acc[2][bb] = fmaf(v2, hv, acc[2][bb]);
                    acc[3][bb] = fmaf(v3, hv, acc[3][bb]);
                }
            }
        }

        // butterfly reduce across the 8 K-slice lanes (width 8)
#pragma unroll
        for (int off = 4; off > 0; off >>= 1)
#pragma unroll
            for (int q = 0; q < 4; q++)
#pragma unroll
                for (int bb = 0; bb < 8; bb++)
                    acc[q][bb] += __shfl_xor_sync(0xffffffffu, acc[q][bb], off, 8);

        // each lane now handles its own batch (bb == kslice)
        float gi = xpi + acc[0][kslice];
        float gf = xpf + acc[1][kslice];
        float gg = xpg + acc[2][kslice];
        float go = xpo + acc[3][kslice];
        float iv = sigf(gi);
        float fv = sigf(gf);
        float gv = tanhf(gg);
        float ov = sigf(go);
        c_reg = fv * c_reg + iv * gv;
        float hv = ov * tanhf(c_reg);

        out[((size_t)myb * SEQ + t) * HID + jg] = hv;
        __stcg(&g_hbuf[(t + 1) & 1][myb][jg], hv);

        if (t == SEQ - 1) {
            // state_h, state_c appended after encoder_outputs (only if they fit)
            if (out_size >= NTOK * HID + 2 * BATCH * HID) {
                float* sh = out + (size_t)NTOK * HID;
                float* sc = sh + (size_t)BATCH * HID;
                sh[(size_t)myb * HID + jg] = hv;
                sc[(size_t)myb * HID + jg] = c_reg;
            }
        } else {
            grid_barrier(gen0 + 1 + t);
        }
    }
}

// =====================================================================
extern "C" void kernel_launch(void* const* d_in, const int* in_sizes, int n_in,
                              void* d_out, int out_size)
{
    (void)in_sizes; (void)n_in;
    const int*   x   = (const int*)d_in[0];     // int32 (JAX default x64-disabled)
    const float* emb = (const float*)d_in[1];
    const float* Wih = (const float*)d_in[2];
    const float* Whh = (const float*)d_in[3];
    const float* bih = (const float*)d_in[4];
    const float* bhh = (const float*)d_in[5];
    float*       out = (float*)d_out;

    dim3 g1(G4 / BN, NTOK / BM);
    xproj_kernel<<<g1, 256>>>(x, emb, Wih, bih, bhh);

    const int smem = (GROWS * WPAD + BATCH * KC) * (int)sizeof(float);  // ~164.9 KB
    cudaFuncSetAttribute(lstm_kernel, cudaFuncAttributeMaxDynamicSharedMemorySize, smem);
    lstm_kernel<<<128, RT, smem>>>(Whh, out, out_size);
}

// round 3
// speedup vs baseline: 1.4175x; 1.4175x over previous
#include <cuda_runtime.h>
#include <cstdint>

#define VOCAB 32000
#define EMB   512
#define HID   1024
#define BATCH 32
#define SEQ   512
#define G4    4096               // 4*HID
#define NTOK  (BATCH*SEQ)        // 16384

// ---------------- scratch (static device allocations only) ----------------
__device__ float g_xproj[(size_t)NTOK * G4];     // 256 MB: [token][gate]
__device__ float g_hbuf[2][BATCH * HID];         // double-buffered h state
__device__ unsigned g_bar_gen;                   // monotonic barrier generation
__device__ unsigned g_bar_cnt;                   // arrival counter (returns to 0)

// =====================================================================
// Kernel 1: x_proj = gather(emb_table, x) @ W_ih^T + (b_ih + b_hh)
// C[16384,4096], K=512. SGEMM 128x128x8, 256 thr, 8x8 microtile,
// double-buffered smem, 1 sync/iter, 2 blocks/SM.
// =====================================================================
#define XBM 128
#define XBN 128
#define XBK 8
#define XKT (EMB / XBK)          // 64 k-tiles

__global__ void __launch_bounds__(256, 2) xproj_kernel(
    const int* __restrict__ x,              // int32 tokens
    const float* __restrict__ emb,
    const float* __restrict__ Wih,
    const float* __restrict__ bih,
    const float* __restrict__ bhh)
{
    __shared__ float As[2][XBK][XBM];
    __shared__ float Bs[2][XBK][XBN];

    const int tid = threadIdx.x;
    const int m0 = blockIdx.y * XBM;
    const int n0 = blockIdx.x * XBN;

    // loaders: 2 threads per row, float4 each
    const int lrow = tid >> 1;          // 0..127
    const int lk   = (tid & 1) * 4;     // 0 or 4
    int erow = x[m0 + lrow];
    erow = max(0, min(VOCAB - 1, erow));
    const float* aptr = emb + (size_t)erow * EMB + lk;
    const float* bptr = Wih + (size_t)(n0 + lrow) * EMB + lk;

    const int ty = tid >> 4;            // 0..15
    const int tx = tid & 15;            // 0..15
    const int mt = ty * 8;
    const int nt = tx * 8;

    float acc[8][8];
#pragma unroll
    for (int i = 0; i < 8; i++)
#pragma unroll
        for (int j = 0; j < 8; j++) acc[i][j] = 0.f;

    // prologue: tile 0 -> smem buf0, tile 1 -> regs
    float4 av = *(const float4*)(aptr);
    float4 bv = *(const float4*)(bptr);
    As[0][lk + 0][lrow] = av.x; As[0][lk + 1][lrow] = av.y;
    As[0][lk + 2][lrow] = av.z; As[0][lk + 3][lrow] = av.w;
    Bs[0][lk + 0][lrow] = bv.x; Bs[0][lk + 1][lrow] = bv.y;
    Bs[0][lk + 2][lrow] = bv.z; Bs[0][lk + 3][lrow] = bv.w;
    av = *(const float4*)(aptr + XBK);
    bv = *(const float4*)(bptr + XBK);
    __syncthreads();

    for (int it = 0; it < XKT; ++it) {
        const int cur = it & 1;
        if (it < XKT - 1) {
            const int nxt = cur ^ 1;
            As[nxt][lk + 0][lrow] = av.x; As[nxt][lk + 1][lrow] = av.y;
            As[nxt][lk + 2][lrow] = av.z; As[nxt][lk + 3][lrow] = av.w;
            Bs[nxt][lk + 0][lrow] = bv.x; Bs[nxt][lk + 1][lrow] = bv.y;
            Bs[nxt][lk + 2][lrow] = bv.z; Bs[nxt][lk + 3][lrow] = bv.w;
        }
        if (it < XKT - 2) {
            av = *(const float4*)(aptr + (it + 2) * XBK);
            bv = *(const float4*)(bptr + (it + 2) * XBK);
        }
#pragma unroll
        for (int k = 0; k < XBK; ++k) {
            float a[8], b[8];
            *(float4*)(a)     = *(const float4*)&As[cur][k][mt];
            *(float4*)(a + 4) = *(const float4*)&As[cur][k][mt + 4];
            *(float4*)(b)     = *(const float4*)&Bs[cur][k][nt];
            *(float4*)(b + 4) = *(const float4*)&Bs[cur][k][nt + 4];
#pragma unroll
            for (int i = 0; i < 8; i++)
#pragma unroll
                for (int j = 0; j < 8; j++)
                    acc[i][j] = fmaf(a[i], b[j], acc[i][j]);
        }
        __syncthreads();
    }

    float bias[8];
#pragma unroll
    for (int j = 0; j < 8; j++) bias[j] = bih[n0 + nt + j] + bhh[n0 + nt + j];
#pragma unroll
    for (int i = 0; i < 8; i++) {
        const size_t row = (size_t)(m0 + mt + i);
        float4 o0, o1;
        o0.x = acc[i][0] + bias[0]; o0.y = acc[i][1] + bias[1];
        o0.z = acc[i][2] + bias[2]; o0.w = acc[i][3] + bias[3];
        o1.x = acc[i][4] + bias[4]; o1.y = acc[i][5] + bias[5];
        o1.z = acc[i][6] + bias[6]; o1.w = acc[i][7] + bias[7];
        *(float4*)&g_xproj[row * G4 + n0 + nt]     = o0;
        *(float4*)&g_xproj[row * G4 + n0 + nt + 4] = o1;
    }
}

// =====================================================================
// Kernel 2: persistent LSTM recurrence. 128 blocks x 512 threads.
// Block owns 8 j-units; W_hh slice (32 rows) lives in smem for the whole
// sequence. 16-wide K-slicing, KC=512 chunks with register prefetch,
// x_proj prefetched across the grid barrier.
// =====================================================================
#define JB    8           // j units per block
#define GROWS 32          // 4*JB weight rows
#define WPAD  1040        // row stride (mod 32 == 16 -> conflict-free)
#define KC    512         // K chunk
#define RT    512         // threads
#define NKS   16          // k slices

__device__ __forceinline__ float sigf(float v) {
    return 1.f / (1.f + __expf(-v));
}

__device__ __forceinline__ void grid_barrier(unsigned target) {
    __syncthreads();
    if (threadIdx.x == 0) {
        __threadfence();
        unsigned prev = atomicAdd(&g_bar_cnt, 1u);
        if (prev == gridDim.x - 1) {
            atomicExch(&g_bar_cnt, 0u);
            __threadfence();
            atomicExch(&g_bar_gen, target);
        } else {
            while ((int)(*(volatile unsigned*)&g_bar_gen - target) < 0) { }
        }
        __threadfence();
    }
    __syncthreads();
}

__device__ __forceinline__ void accum_chunk(
    const float* __restrict__ hsb,      // hs + b0*KC
    const float* __restrict__ w0, const float* __restrict__ w1,
    const float* __restrict__ w2, const float* __restrict__ w3,
    int kslice, float acc[4][8])
{
#pragma unroll 8
    for (int kk = 0; kk < KC / NKS; ++kk) {       // 32 iters
        const int kl = kk * NKS + kslice;
        const float v0 = w0[kl], v1 = w1[kl], v2 = w2[kl], v3 = w3[kl];
#pragma unroll
        for (int bb = 0; bb < 8; ++bb) {
            const float hv = hsb[bb * KC + kl];
            acc[0][bb] = fmaf(v0, hv, acc[0][bb]);
            acc[1][bb] = fmaf(v1, hv, acc[1][bb]);
            acc[2][bb] = fmaf(v2, hv, acc[2][bb]);
            acc[3][bb] = fmaf(v3, hv, acc[3][bb]);
        }
    }
}

__global__ void __launch_bounds__(RT, 1) lstm_kernel(
    const float* __restrict__ Whh,
    float* __restrict__ out,
    int out_size)
{
    extern __shared__ float sm[];
    float* w_s = sm;                      // [32][WPAD]
    float* hs  = sm + GROWS * WPAD;       // [BATCH][KC]

    const int tid = threadIdx.x;
    const int bid = blockIdx.x;
    const int j0  = bid * JB;

    const unsigned gen0 = *(volatile unsigned*)&g_bar_gen;

    // ---- load this block's W_hh slice (once) ----
    for (int idx = tid; idx < GROWS * (HID / 4); idx += RT) {
        const int r  = idx >> 8;              // /(HID/4)
        const int k4 = idx & 255;
        const int q  = r >> 3, jl = r & 7;
        float4 v = ((const float4*)Whh)[(size_t)(q * HID + j0 + jl) * (HID / 4) + k4];
        ((float4*)(w_s + r * WPAD))[k4] = v;
    }

    // thread decomposition: 32 items (jl x batch-group) x 16 K-slices
    const int kslice = tid & 15;
    const int item   = tid >> 4;
    const int jl     = item & 7;
    const int bg     = item >> 3;             // 0..3
    const int b0     = bg * 8;
    const int jg     = j0 + jl;
    const bool owner = (kslice < 8);
    const int myb    = b0 + (kslice & 7);     // valid for owners

    const float* wb0 = w_s + (0 * JB + jl) * WPAD;
    const float* wb1 = w_s + (1 * JB + jl) * WPAD;
    const float* wb2 = w_s + (2 * JB + jl) * WPAD;
    const float* wb3 = w_s + (3 * JB + jl) * WPAD;

    float c_reg = 0.f;

    // ---- t = 0: h_prev = 0 -> gates are just x_proj ----
    if (owner) {
        const float* xp = g_xproj + (size_t)myb * SEQ * G4;
        float iv = sigf(__ldcg(xp + 0 * HID + jg));
        float gv = tanhf(__ldcg(xp + 2 * HID + jg));
        float ov = sigf(__ldcg(xp + 3 * HID + jg));
        c_reg = iv * gv;
        float hv = ov * tanhf(c_reg);
        out[(size_t)myb * SEQ * HID + jg] = hv;
        __stcg(&g_hbuf[1][myb * HID + jg], hv);
    }

    // prefetch x_proj for t=1 (independent of h -> hide under barrier)
    float xpi = 0.f, xpf = 0.f, xpg = 0.f, xpo = 0.f;
    if (owner) {
        const float* xp = g_xproj + ((size_t)myb * SEQ + 1) * G4;
        xpi = __ldcg(xp + 0 * HID + jg);
        xpf = __ldcg(xp + 1 * HID + jg);
        xpg = __ldcg(xp + 2 * HID + jg);
        xpo = __ldcg(xp + 3 * HID + jg);
    }
    grid_barrier(gen0 + 1);

    // ---- t = 1 .. 511 ----
    for (int t = 1; t < SEQ; ++t) {
        const float4* hsrc4 = (const float4*)g_hbuf[t & 1];

        float acc[4][8];
#pragma unroll
        for (int q = 0; q < 4; q++)
#pragma unroll
            for (int bb = 0; bb < 8; bb++) acc[q][bb] = 0.f;

        // stage chunk 0 (8 float4/thread), prefetch chunk 1 during compute
        float4 pre[8];
#pragma unroll
        for (int i = 0; i < 8; ++i) {
            const int idx = tid + i * RT;
            pre[i] = __ldcg(hsrc4 + (idx >> 7) * (HID / 4) + (idx & 127));
        }
#pragma unroll
        for (int i = 0; i < 8; ++i)
            ((float4*)hs)[tid + i * RT] = pre[i];
        __syncthreads();

        // issue chunk-1 global loads (in flight during chunk-0 compute)
#pragma unroll
        for (int i = 0; i < 8; ++i) {
            const int idx = tid + i * RT;
            pre[i] = __ldcg(hsrc4 + (idx >> 7) * (HID / 4) + (KC / 4) + (idx & 127));
        }

        accum_chunk(hs + b0 * KC, wb0, wb1, wb2, wb3, kslice, acc);
        __syncthreads();

#pragma unroll
        for (int i = 0; i < 8; ++i)
            ((float4*)hs)[tid + i * RT] = pre[i];
        __syncthreads();

        accum_chunk(hs + b0 * KC, wb0 + KC, wb1 + KC, wb2 + KC, wb3 + KC,
                    kslice, acc);

        // butterfly reduce across 16 K-slice lanes
#pragma unroll
        for (int off = 8; off; off >>= 1)
#pragma unroll
            for (int q = 0; q < 4; q++)
#pragma unroll
                for (int bb = 0; bb < 8; bb++)
                    acc[q][bb] += __shfl_xor_sync(0xffffffffu, acc[q][bb], off, NKS);

        if (owner) {
            // static-index select of this lane's batch column (no spill)
            float g0 = acc[0][0], g1 = acc[1][0], g2 = acc[2][0], g3 = acc[3][0];
#pragma unroll
            for (int bb = 1; bb < 8; ++bb) {
                if (kslice == bb) {
                    g0 = acc[0][bb]; g1 = acc[1][bb];
                    g2 = acc[2][bb]; g3 = acc[3][bb];
                }
            }
            const float iv = sigf(xpi + g0);
            const float fv = sigf(xpf + g1);
            const float gv = tanhf(xpg + g2);
            const float ov = sigf(xpo + g3);
            c_reg = fv * c_reg + iv * gv;
            const float hv = ov * tanhf(c_reg);

            out[((size_t)myb * SEQ + t) * HID + jg] = hv;
            __stcg(&g_hbuf[(t + 1) & 1][myb * HID + jg], hv);

            if (t == SEQ - 1) {
                if (out_size >= NTOK * HID + 2 * BATCH * HID) {
                    float* sh = out + (size_t)NTOK * HID;
                    float* sc = sh + (size_t)BATCH * HID;
                    sh[(size_t)myb * HID + jg] = hv;
                    sc[(size_t)myb * HID + jg] = c_reg;
                }
            } else {
                // prefetch x_proj for t+1 before the barrier spin
                const float* xp = g_xproj + ((size_t)myb * SEQ + t + 1) * G4;
                xpi = __ldcg(xp + 0 * HID + jg);
                xpf = __ldcg(xp + 1 * HID + jg);
                xpg = __ldcg(xp + 2 * HID + jg);
                xpo = __ldcg(xp + 3 * HID + jg);
            }
        }
        if (t < SEQ - 1) grid_barrier(gen0 + 1 + t);
    }
}

// =====================================================================
extern "C" void kernel_launch(void* const* d_in, const int* in_sizes, int n_in,
                              void* d_out, int out_size)
{
    (void)in_sizes; (void)n_in;
    const int*   x   = (const int*)d_in[0];
    const float* emb = (const float*)d_in[1];
    const float* Wih = (const float*)d_in[2];
    const float* Whh = (const float*)d_in[3];
    const float* bih = (const float*)d_in[4];
    const float* bhh = (const float*)d_in[5];
    float*       out = (float*)d_out;

    dim3 g1(G4 / XBN, NTOK / XBM);          // (32, 128)
    xproj_kernel<<<g1, 256>>>(x, emb, Wih, bih, bhh);

    const int smem = (GROWS * WPAD + BATCH * KC) * (int)sizeof(float);  // 198656 B
    cudaFuncSetAttribute(lstm_kernel, cudaFuncAttributeMaxDynamicSharedMemorySize, smem);
    lstm_kernel<<<128, RT, smem>>>(Whh, out, out_size);
}

// round 4
// speedup vs baseline: 1.4919x; 1.0525x over previous
#include <cuda_runtime.h>
#include <cstdint>

#define VOCAB 32000
#define EMB   512
#define HID   1024
#define BATCH 32
#define SEQ   512
#define G4    4096               // 4*HID
#define NTOK  (BATCH*SEQ)        // 16384

// ---------------- scratch (static device allocations only) ----------------
__device__ float g_xproj[(size_t)NTOK * G4];     // 256 MB: [token][gate]
__device__ float g_hbuf[2][BATCH * HID];         // double-buffered h state
__device__ unsigned g_bar_gen;                   // monotonic barrier generation
__device__ unsigned g_bar_cnt;                   // arrival counter (returns to 0)

// =====================================================================
// Kernel 1: x_proj = gather(emb_table, x) @ W_ih^T + (b_ih + b_hh)
// tf32 tensor-core GEMM with 3-term compensation (fp32-accurate).
// C[16384,4096], K=512. Block 128x128x32, 256 thr (8 warps, 2x4),
// warp tile 64x32 via m16n8k8. Double-buffered smem + reg prefetch.
// =====================================================================
#define XBM 128
#define XBN 128
#define XBK 32
#define XPAD 36                  // smem row stride (floats): conflict-free frags
#define XKT (EMB / XBK)          // 16 outer k-iters

__device__ __forceinline__ uint32_t f2tf32(float f) {
    uint32_t r;
    asm volatile("cvt.rna.tf32.f32 %0, %1;" : "=r"(r) : "f"(f));
    return r;
}

__device__ __forceinline__ void mma_tf32(float c[4],
    uint32_t a0, uint32_t a1, uint32_t a2, uint32_t a3,
    uint32_t b0, uint32_t b1)
{
    asm volatile(
        "mma.sync.aligned.m16n8k8.row.col.f32.tf32.tf32.f32 "
        "{%0,%1,%2,%3}, {%4,%5,%6,%7}, {%8,%9}, {%0,%1,%2,%3};\n"
        : "+f"(c[0]), "+f"(c[1]), "+f"(c[2]), "+f"(c[3])
        : "r"(a0), "r"(a1), "r"(a2), "r"(a3), "r"(b0), "r"(b1));
}

__global__ void __launch_bounds__(256, 1) xproj_kernel(
    const int* __restrict__ x,              // int32 tokens
    const float* __restrict__ emb,
    const float* __restrict__ Wih,
    const float* __restrict__ bih,
    const float* __restrict__ bhh)
{
    extern __shared__ float xsm[];
    float* As = xsm;                          // [2][128][XPAD]
    float* Bs = xsm + 2 * XBM * XPAD;         // [2][128][XPAD]

    const int tid  = threadIdx.x;
    const int lane = tid & 31;
    const int wid  = tid >> 5;                // 0..7
    const int m0 = blockIdx.y * XBM;
    const int n0 = blockIdx.x * XBN;

    // ---- loaders: 2 threads per row, 16 consecutive floats each ----
    const int lrow = tid >> 1;                // 0..127
    const int lk   = (tid & 1) * 16;          // 0 or 16
    int erow = x[m0 + lrow];
    erow = max(0, min(VOCAB - 1, erow));
    const float* aptr = emb + (size_t)erow * EMB + lk;
    const float* bptr = Wih + (size_t)(n0 + lrow) * EMB + lk;
    float* asdst = As + lrow * XPAD + lk;     // + buf*XBM*XPAD
    float* bsdst = Bs + lrow * XPAD + lk;

    // ---- warp tile: 2x4 grid of 64x32 ----
    const int wm = (wid >> 2) * 64;           // 0 or 64
    const int wn = (wid & 3) * 32;            // 0,32,64,96
    const int ar = lane >> 2;                 // 0..7
    const int ac = lane & 3;                  // 0..3

    float acc[4][4][4];                       // [mt][nt][frag]
#pragma unroll
    for (int mt = 0; mt < 4; mt++)
#pragma unroll
        for (int nt = 0; nt < 4; nt++)
#pragma unroll
            for (int q = 0; q < 4; q++) acc[mt][nt][q] = 0.f;

    // prologue: iter0 -> smem buf0; iter1 -> regs
    float4 avr[4], bvr[4];
#pragma unroll
    for (int q = 0; q < 4; q++) {
        float4 av = *(const float4*)(aptr + q * 4);
        float4 bv = *(const float4*)(bptr + q * 4);
        *(float4*)(asdst + q * 4) = av;
        *(float4*)(bsdst + q * 4) = bv;
    }
#pragma unroll
    for (int q = 0; q < 4; q++) {
        avr[q] = *(const float4*)(aptr + XBK + q * 4);
        bvr[q] = *(const float4*)(bptr + XBK + q * 4);
    }
    __syncthreads();

    for (int it = 0; it < XKT; ++it) {
        const int cur = it & 1;
        if (it < XKT - 1) {
            const int nb = (cur ^ 1) * XBM * XPAD;
#pragma unroll
            for (int q = 0; q < 4; q++) {
                *(float4*)(asdst + nb + q * 4) = avr[q];
                *(float4*)(bsdst + nb + q * 4) = bvr[q];
            }
        }
        if (it < XKT - 2) {
#pragma unroll
            for (int q = 0; q < 4; q++) {
                avr[q] = *(const float4*)(aptr + (it + 2) * XBK + q * 4);
                bvr[q] = *(const float4*)(bptr + (it + 2) * XBK + q * 4);
            }
        }

        const float* Ab = As + cur * XBM * XPAD;
        const float* Bb = Bs + cur * XBM * XPAD;

#pragma unroll
        for (int ksi = 0; ksi < 4; ++ksi) {
            const int ks = ksi * 8;
            uint32_t ah[4][4], al[4][4];
#pragma unroll
            for (int mt = 0; mt < 4; ++mt) {
                const float* p = Ab + (wm + mt * 16 + ar) * XPAD + ks + ac;
                float v0 = p[0];
                float v1 = p[8 * XPAD];
                float v2 = p[4];
                float v3 = p[8 * XPAD + 4];
                ah[mt][0] = f2tf32(v0); al[mt][0] = f2tf32(v0 - __uint_as_float(ah[mt][0]));
                ah[mt][1] = f2tf32(v1); al[mt][1] = f2tf32(v1 - __uint_as_float(ah[mt][1]));
                ah[mt][2] = f2tf32(v2); al[mt][2] = f2tf32(v2 - __uint_as_float(ah[mt][2]));
                ah[mt][3] = f2tf32(v3); al[mt][3] = f2tf32(v3 - __uint_as_float(ah[mt][3]));
            }
            uint32_t bh[4][2], bl[4][2];
#pragma unroll
            for (int nt = 0; nt < 4; ++nt) {
                const float* p = Bb + (wn + nt * 8 + ar) * XPAD + ks + ac;
                float v0 = p[0];
                float v1 = p[4];
                bh[nt][0] = f2tf32(v0); bl[nt][0] = f2tf32(v0 - __uint_as_float(bh[nt][0]));
                bh[nt][1] = f2tf32(v1); bl[nt][1] = f2tf32(v1 - __uint_as_float(bh[nt][1]));
            }
#pragma unroll
            for (int mt = 0; mt < 4; ++mt)
#pragma unroll
                for (int nt = 0; nt < 4; ++nt) {
                    mma_tf32(acc[mt][nt], ah[mt][0], ah[mt][1], ah[mt][2], ah[mt][3],
                             bh[nt][0], bh[nt][1]);
                    mma_tf32(acc[mt][nt], ah[mt][0], ah[mt][1], ah[mt][2], ah[mt][3],
                             bl[nt][0], bl[nt][1]);
                    mma_tf32(acc[mt][nt], al[mt][0], al[mt][1], al[mt][2], al[mt][3],
                             bh[nt][0], bh[nt][1]);
                }
        }
        __syncthreads();
    }

    // ---- epilogue: bias + store ----
    float bias0[4], bias1[4];
#pragma unroll
    for (int nt = 0; nt < 4; ++nt) {
        const int n_g = n0 + wn + nt * 8 + (lane & 3) * 2;
        bias0[nt] = bih[n_g]     + bhh[n_g];
        bias1[nt] = bih[n_g + 1] + bhh[n_g + 1];
    }
#pragma unroll
    for (int mt = 0; mt < 4; ++mt) {
        const int m_g = m0 + wm + mt * 16 + (lane >> 2);
#pragma unroll
        for (int nt = 0; nt < 4; ++nt) {
            const int n_g = n0 + wn + nt * 8 + (lane & 3) * 2;
            float2 r0, r1;
            r0.x = acc[mt][nt][0] + bias0[nt];
            r0.y = acc[mt][nt][1] + bias1[nt];
            r1.x = acc[mt][nt][2] + bias0[nt];
            r1.y = acc[mt][nt][3] + bias1[nt];
            *(float2*)&g_xproj[(size_t)m_g * G4 + n_g]       = r0;
            *(float2*)&g_xproj[(size_t)(m_g + 8) * G4 + n_g] = r1;
        }
    }
}

// =====================================================================
// Kernel 2: persistent LSTM recurrence (unchanged from round 3).
// =====================================================================
#define JB    8           // j units per block
#define GROWS 32          // 4*JB weight rows
#define WPAD  1040        // row stride (mod 32 == 16 -> conflict-free)
#define KC    512         // K chunk
#define RT    512         // threads
#define NKS   16          // k slices

__device__ __forceinline__ float sigf(float v) {
    return 1.f / (1.f + __expf(-v));
}

__device__ __forceinline__ void grid_barrier(unsigned target) {
    __syncthreads();
    if (threadIdx.x == 0) {
        __threadfence();
        unsigned prev = atomicAdd(&g_bar_cnt, 1u);
        if (prev == gridDim.x - 1) {
            atomicExch(&g_bar_cnt, 0u);
            __threadfence();
            atomicExch(&g_bar_gen, target);
        } else {
            while ((int)(*(volatile unsigned*)&g_bar_gen - target) < 0) { }
        }
        __threadfence();
    }
    __syncthreads();
}

__device__ __forceinline__ void accum_chunk(
    const float* __restrict__ hsb,      // hs + b0*KC
    const float* __restrict__ w0, const float* __restrict__ w1,
    const float* __restrict__ w2, const float* __restrict__ w3,
    int kslice, float acc[4][8])
{
#pragma unroll 8
    for (int kk = 0; kk < KC / NKS; ++kk) {       // 32 iters
        const int kl = kk * NKS + kslice;
        const float v0 = w0[kl], v1 = w1[kl], v2 = w2[kl], v3 = w3[kl];
#pragma unroll
        for (int bb = 0; bb < 8; ++bb) {
            const float hv = hsb[bb * KC + kl];
            acc[0][bb] = fmaf(v0, hv, acc[0][bb]);
            acc[1][bb] = fmaf(v1, hv, acc[1][bb]);
            acc[2][bb] = fmaf(v2, hv, acc[2][bb]);
            acc[3][bb] = fmaf(v3, hv, acc[3][bb]);
        }
    }
}

__global__ void __launch_bounds__(RT, 1) lstm_kernel(
    const float* __restrict__ Whh,
    float* __restrict__ out,
    int out_size)
{
    extern __shared__ float sm[];
    float* w_s = sm;                      // [32][WPAD]
    float* hs  = sm + GROWS * WPAD;       // [BATCH][KC]

    const int tid = threadIdx.x;
    const int bid = blockIdx.x;
    const int j0  = bid * JB;

    const unsigned gen0 = *(volatile unsigned*)&g_bar_gen;

    // ---- load this block's W_hh slice (once) ----
    for (int idx = tid; idx < GROWS * (HID / 4); idx += RT) {
        const int r  = idx >> 8;              // /(HID/4)
        const int k4 = idx & 255;
        const int q  = r >> 3, jl = r & 7;
        float4 v = ((const float4*)Whh)[(size_t)(q * HID + j0 + jl) * (HID / 4) + k4];
        ((float4*)(w_s + r * WPAD))[k4] = v;
    }

    // thread decomposition: 32 items (jl x batch-group) x 16 K-slices
    const int kslice = tid & 15;
    const int item   = tid >> 4;
    const int jl     = item & 7;
    const int bg     = item >> 3;             // 0..3
    const int b0     = bg * 8;
    const int jg     = j0 + jl;
    const bool owner = (kslice < 8);
    const int myb    = b0 + (kslice & 7);     // valid for owners

    const float* wb0 = w_s + (0 * JB + jl) * WPAD;
    const float* wb1 = w_s + (1 * JB + jl) * WPAD;
    const float* wb2 = w_s + (2 * JB + jl) * WPAD;
    const float* wb3 = w_s + (3 * JB + jl) * WPAD;

    float c_reg = 0.f;

    // ---- t = 0: h_prev = 0 -> gates are just x_proj ----
    if (owner) {
        const float* xp = g_xproj + (size_t)myb * SEQ * G4;
        float iv = sigf(__ldcg(xp + 0 * HID + jg));
        float gv = tanhf(__ldcg(xp + 2 * HID + jg));
        float ov = sigf(__ldcg(xp + 3 * HID + jg));
        c_reg = iv * gv;
        float hv = ov * tanhf(c_reg);
        out[(size_t)myb * SEQ * HID + jg] = hv;
        __stcg(&g_hbuf[1][myb * HID + jg], hv);
    }

    // prefetch x_proj for t=1 (independent of h -> hide under barrier)
    float xpi = 0.f, xpf = 0.f, xpg = 0.f, xpo = 0.f;
    if (owner) {
        const float* xp = g_xproj + ((size_t)myb * SEQ + 1) * G4;
        xpi = __ldcg(xp + 0 * HID + jg);
        xpf = __ldcg(xp + 1 * HID + jg);
        xpg = __ldcg(xp + 2 * HID + jg);
        xpo = __ldcg(xp + 3 * HID + jg);
    }
    grid_barrier(gen0 + 1);

    // ---- t = 1 .. 511 ----
    for (int t = 1; t < SEQ; ++t) {
        const float4* hsrc4 = (const float4*)g_hbuf[t & 1];

        float acc[4][8];
#pragma unroll
        for (int q = 0; q < 4; q++)
#pragma unroll
            for (int bb = 0; bb < 8; bb++) acc[q][bb] = 0.f;

        // stage chunk 0 (8 float4/thread), prefetch chunk 1 during compute
        float4 pre[8];
#pragma unroll
        for (int i = 0; i < 8; ++i) {
            const int idx = tid + i * RT;
            pre[i] = __ldcg(hsrc4 + (idx >> 7) * (HID / 4) + (idx & 127));
        }
#pragma unroll
        for (int i = 0; i < 8; ++i)
            ((float4*)hs)[tid + i * RT] = pre[i];
        __syncthreads();

        // issue chunk-1 global loads (in flight during chunk-0 compute)
#pragma unroll
        for (int i = 0; i < 8; ++i) {
            const int idx = tid + i * RT;
            pre[i] = __ldcg(hsrc4 + (idx >> 7) * (HID / 4) + (KC / 4) + (idx & 127));
        }

        accum_chunk(hs + b0 * KC, wb0, wb1, wb2, wb3, kslice, acc);
        __syncthreads();

#pragma unroll
        for (int i = 0; i < 8; ++i)
            ((float4*)hs)[tid + i * RT] = pre[i];
        __syncthreads();

        accum_chunk(hs + b0 * KC, wb0 + KC, wb1 + KC, wb2 + KC, wb3 + KC,
                    kslice, acc);

        // butterfly reduce across 16 K-slice lanes
#pragma unroll
        for (int off = 8; off; off >>= 1)
#pragma unroll
            for (int q = 0; q < 4; q++)
#pragma unroll
                for (int bb = 0; bb < 8; bb++)
                    acc[q][bb] += __shfl_xor_sync(0xffffffffu, acc[q][bb], off, NKS);

        if (owner) {
            // static-index select of this lane's batch column (no spill)
            float g0 = acc[0][0], g1 = acc[1][0], g2 = acc[2][0], g3 = acc[3][0];
#pragma unroll
            for (int bb = 1; bb < 8; ++bb) {
                if (kslice == bb) {
                    g0 = acc[0][bb]; g1 = acc[1][bb];
                    g2 = acc[2][bb]; g3 = acc[3][bb];
                }
            }
            const float iv = sigf(xpi + g0);
            const float fv = sigf(xpf + g1);
            const float gv = tanhf(xpg + g2);
            const float ov = sigf(xpo + g3);
            c_reg = fv * c_reg + iv * gv;
            const float hv = ov * tanhf(c_reg);

            out[((size_t)myb * SEQ + t) * HID + jg] = hv;
            __stcg(&g_hbuf[(t + 1) & 1][myb * HID + jg], hv);

            if (t == SEQ - 1) {
                if (out_size >= NTOK * HID + 2 * BATCH * HID) {
                    float* sh = out + (size_t)NTOK * HID;
                    float* sc = sh + (size_t)BATCH * HID;
                    sh[(size_t)myb * HID + jg] = hv;
                    sc[(size_t)myb * HID + jg] = c_reg;
                }
            } else {
                // prefetch x_proj for t+1 before the barrier spin
                const float* xp = g_xproj + ((size_t)myb * SEQ + t + 1) * G4;
                xpi = __ldcg(xp + 0 * HID + jg);
                xpf = __ldcg(xp + 1 * HID + jg);
                xpg = __ldcg(xp + 2 * HID + jg);
                xpo = __ldcg(xp + 3 * HID + jg);
            }
        }
        if (t < SEQ - 1) grid_barrier(gen0 + 1 + t);
    }
}

// =====================================================================
extern "C" void kernel_launch(void* const* d_in, const int* in_sizes, int n_in,
                              void* d_out, int out_size)
{
    (void)in_sizes; (void)n_in;
    const int*   x   = (const int*)d_in[0];
    const float* emb = (const float*)d_in[1];
    const float* Wih = (const float*)d_in[2];
    const float* Whh = (const float*)d_in[3];
    const float* bih = (const float*)d_in[4];
    const float* bhh = (const float*)d_in[5];
    float*       out = (float*)d_out;

    const int xsmem = 4 * XBM * XPAD * (int)sizeof(float);   // 73728 B
    cudaFuncSetAttribute(xproj_kernel, cudaFuncAttributeMaxDynamicSharedMemorySize, xsmem);
    dim3 g1(G4 / XBN, NTOK / XBM);          // (32, 128)
    xproj_kernel<<<g1, 256, xsmem>>>(x, emb, Wih, bih, bhh);

    const int smem = (GROWS * WPAD + BATCH * KC) * (int)sizeof(float);  // 198656 B
    cudaFuncSetAttribute(lstm_kernel, cudaFuncAttributeMaxDynamicSharedMemorySize, smem);
    lstm_kernel<<<128, RT, smem>>>(Whh, out, out_size);
}